// round 12
// baseline (speedup 1.0000x reference)
#include <cuda_runtime.h>
#include <cuda_bf16.h>
#include <cstdint>
#include <math.h>

#define L 8192
#define K 48
#define SENTK 0xFFFFFFFFFFFFFFFFULL
typedef unsigned long long ull;

#define M_EDGES (L * K)          // 393216
#define N_TILES (M_EDGES / 128)  // 3072

// ---------------- device scratch (static; allocation-free) ----------------
__device__ __align__(16) float g_A[L * 128];
__device__ __align__(16) float g_B[L * 128];
__device__ __align__(16) float g_WAT[128 * 128];
__device__ __align__(16) float g_WfT[128 * 128];
__device__ __align__(16) float g_WhT[128 * 128];
__device__ __align__(16) float g_w1[128];
__device__ __align__(16) float g_c0[128];
__device__ uint4 g_WpFrag[4 * 8 * 2 * 2 * 32];   // [nsl][ks8][nb][hl][lane]
__device__ uint4 g_WsmFrag[4 * 2 * 2 * 2 * 32];  // [nsl][ks2][nb][hl][lane]
__device__ int   g_knn_idx[L * K];
__device__ float g_knn_d[L * K];
__device__ __align__(16) __nv_bfloat16 g_Ehi[(size_t)M_EDGES * 128];
__device__ __align__(16) __nv_bfloat16 g_Elo[(size_t)M_EDGES * 128];
__device__ float g_mean[M_EDGES];
__device__ float g_rstd[M_EDGES];

// ---------------- helpers ----------------
__device__ __forceinline__ uint32_t smem_u32(const void* p) {
    uint32_t a;
    asm("{ .reg .u64 t; cvta.to.shared.u64 t, %1; cvt.u32.u64 %0, t; }" : "=r"(a) : "l"(p));
    return a;
}
__device__ __forceinline__ void ldm4(uint32_t* r, uint32_t addr) {
    asm volatile("ldmatrix.sync.aligned.m8n8.x4.shared.b16 {%0,%1,%2,%3}, [%4];"
                 : "=r"(r[0]), "=r"(r[1]), "=r"(r[2]), "=r"(r[3]) : "r"(addr));
}
__device__ __forceinline__ void mma_bf16(float* c, const uint32_t* a, const uint32_t* b) {
    asm volatile("mma.sync.aligned.m16n8k16.row.col.f32.bf16.bf16.f32 "
                 "{%0,%1,%2,%3}, {%4,%5,%6,%7}, {%8,%9}, {%0,%1,%2,%3};"
                 : "+f"(c[0]), "+f"(c[1]), "+f"(c[2]), "+f"(c[3])
                 : "r"(a[0]), "r"(a[1]), "r"(a[2]), "r"(a[3]), "r"(b[0]), "r"(b[1]));
}
__device__ __forceinline__ void bf16split(float v, __nv_bfloat16& h, __nv_bfloat16& l) {
    h = __float2bfloat16(v);
    l = __float2bfloat16(v - __bfloat162float(h));
}

// ---------------- tiny precompute (w1/c0 + transposed We blocks) ----------------
__global__ void prep_small_kernel(const float* __restrict__ Wproj,
                                  const float* __restrict__ ln_scale,
                                  const float* __restrict__ ln_bias,
                                  const float* __restrict__ bproj,
                                  const float* __restrict__ We) {
    int gid = blockIdx.x * blockDim.x + threadIdx.x;
    int NT = gridDim.x * blockDim.x;
    for (int n = gid; n < 16384; n += NT) {
        int c = n >> 7, t = n & 127;
        g_WAT[n] = We[t * 416 + 160 + c];
        g_WfT[n] = We[t * 416 + c];
        g_WhT[n] = We[t * 416 + 288 + c];
    }
    if (gid < 128) {
        float s1 = 0.f, s0 = 0.f;
        for (int c = 0; c < 128; c++) {
            float w = Wproj[gid * 128 + c];
            s1 += w * ln_scale[c];
            s0 += w * ln_bias[c];
        }
        g_w1[gid] = s1;
        g_c0[gid] = s0 + bproj[gid];
    }
}

// ---------------- prep_frag: build ldmatrix-exact W fragments in global ----------------
// smem: Wp hi [128n x 136] @0 (34816B), Wp lo @34816, Wsm hi [128n x 40] @69632 (10240B), Wsm lo @79872
#define PF_TOT 90112
__global__ void __launch_bounds__(256, 1) prep_frag_kernel(const float* __restrict__ Wproj,
                                                           const float* __restrict__ ln_scale,
                                                           const float* __restrict__ We) {
    extern __shared__ __align__(16) char psm[];
    uint32_t sb = smem_u32(psm);
    int tid = threadIdx.x;
    for (int n = tid; n < 16384; n += 256) {
        int t = n >> 7, c = n & 127;
        float w = Wproj[t * 128 + c] * ln_scale[c];
        __nv_bfloat16 h, l;
        bf16split(w, h, l);
        *(__nv_bfloat16*)(psm + (size_t)0     + ((size_t)t * 136 + c) * 2) = h;
        *(__nv_bfloat16*)(psm + (size_t)34816 + ((size_t)t * 136 + c) * 2) = l;
    }
    for (int n = tid; n < 4096; n += 256) {
        int c = n >> 5, q = n & 31;
        float w = We[c * 416 + 128 + q];
        __nv_bfloat16 h, l;
        bf16split(w, h, l);
        *(__nv_bfloat16*)(psm + (size_t)69632 + ((size_t)c * 40 + q) * 2) = h;
        *(__nv_bfloat16*)(psm + (size_t)79872 + ((size_t)c * 40 + q) * 2) = l;
    }
    __syncthreads();
    int wid = tid >> 5, lane = tid & 31;
    int g = lane >> 3, ri = lane & 7;
    int nsl = wid & 3;
    // Wproj fragments: warps 0-3 ks 0-3, warps 4-7 ks 4-7
    for (int ks = (wid >> 2) * 4; ks < (wid >> 2) * 4 + 4; ks++) {
#pragma unroll
        for (int nb = 0; nb < 2; nb++) {
#pragma unroll
            for (int hl = 0; hl < 2; hl++) {
                uint32_t off = (uint32_t)((nsl * 32 + nb * 16 + ri + (g >> 1) * 8) * 136 + (g & 1) * 8) * 2
                               + ks * 32 + (hl ? 34816u : 0u);
                uint32_t r[4];
                ldm4(r, sb + off);
                g_WpFrag[(((nsl * 8 + ks) * 2 + nb) * 2 + hl) * 32 + lane] =
                    make_uint4(r[0], r[1], r[2], r[3]);
            }
        }
    }
    // Wsm fragments: warps 0-3 only
    if (wid < 4) {
#pragma unroll
        for (int ks = 0; ks < 2; ks++) {
#pragma unroll
            for (int nb = 0; nb < 2; nb++) {
#pragma unroll
                for (int hl = 0; hl < 2; hl++) {
                    uint32_t off = (uint32_t)((nsl * 32 + nb * 16 + ri + (g >> 1) * 8) * 40 + (g & 1) * 8) * 2
                                   + ks * 32 + (hl ? 79872u : 69632u);
                    uint32_t r[4];
                    ldm4(r, sb + off);
                    g_WsmFrag[(((nsl * 2 + ks) * 2 + nb) * 2 + hl) * 32 + lane] =
                        make_uint4(r[0], r[1], r[2], r[3]);
                }
            }
        }
    }
}

// ---------------- A/B tables ----------------
__global__ void __launch_bounds__(128) prep_ab_kernel(const float* __restrict__ node_h,
                                                      const float* __restrict__ f_node) {
    __shared__ float nh[32 * 128];
    __shared__ float fn[32 * 128];
    int tid = threadIdx.x;
    int i0 = blockIdx.x * 32;
    for (int f = tid; f < 32 * 128; f += 128) {
        nh[f] = node_h[i0 * 128 + f];
        fn[f] = f_node[i0 * 128 + f];
    }
    __syncthreads();
    for (int ch = 0; ch < 4; ch++) {
        float a[8], b[8];
#pragma unroll
        for (int ii = 0; ii < 8; ii++) { a[ii] = 0.f; b[ii] = 0.f; }
#pragma unroll 4
        for (int c = 0; c < 128; c++) {
            float wa = __ldg(g_WAT + c * 128 + tid);
            float wf = __ldg(g_WfT + c * 128 + tid);
            float wh = __ldg(g_WhT + c * 128 + tid);
#pragma unroll
            for (int ii = 0; ii < 8; ii++) {
                int row = ch * 8 + ii;
                float n = nh[row * 128 + c];
                float f = fn[row * 128 + c];
                a[ii] = fmaf(n, wa, a[ii]);
                b[ii] = fmaf(f, wf, fmaf(n, wh, b[ii]));
            }
        }
#pragma unroll
        for (int ii = 0; ii < 8; ii++) {
            g_A[(i0 + ch * 8 + ii) * 128 + tid] = a[ii];
            g_B[(i0 + ch * 8 + ii) * 128 + tid] = b[ii];
        }
    }
}

// ---------------- KNN (R11, passing) ----------------
__global__ void __launch_bounds__(512) knn_kernel(const float* __restrict__ X) {
    extern __shared__ float sx[];
    int tid = threadIdx.x;
    for (int idx = tid; idx < L; idx += 512) {
        sx[idx]         = X[3 * idx];
        sx[L + idx]     = X[3 * idx + 1];
        sx[2 * L + idx] = X[3 * idx + 2];
    }
    __syncthreads();
    int lane = tid & 31;
    int i = blockIdx.x * 16 + (tid >> 5);
    float xi = sx[i], yi = sx[L + i], zi = sx[2 * L + i];

    ull h[8];
#pragma unroll
    for (int m = 0; m < 8; m++) h[m] = SENTK;

#pragma unroll 4
    for (int s = 0; s < L / 32; s++) {
        int j = lane + (s << 5);
        float dx = xi - sx[j], dy = yi - sx[L + j], dz = zi - sx[2 * L + j];
        float ssq = __fadd_rn(__fadd_rn(__fmul_rn(dx, dx), __fmul_rn(dy, dy)), __fmul_rn(dz, dz));
        unsigned sb = __float_as_uint(ssq);
        unsigned hs = (unsigned)(h[7] >> 32);
        if (sb < hs || (sb == hs && (unsigned)j < (unsigned)h[7])) {
            h[7] = ((ull)sb << 32) | (unsigned)j;
#pragma unroll
            for (int m = 7; m > 0; m--)
                if (h[m] < h[m - 1]) { ull t = h[m]; h[m] = h[m - 1]; h[m - 1] = t; }
        }
    }

    ull mylast = 0ULL;
    for (int r = 0; r < K; r++) {
        if (h[0] == SENTK) {
            for (int s = 0; s < L / 32; s++) {
                int j = lane + (s << 5);
                float dx = xi - sx[j], dy = yi - sx[L + j], dz = zi - sx[2 * L + j];
                float ssq = __fadd_rn(__fadd_rn(__fmul_rn(dx, dx), __fmul_rn(dy, dy)), __fmul_rn(dz, dz));
                ull key = ((ull)__float_as_uint(ssq) << 32) | (unsigned)j;
                if (key > mylast && key < h[7]) {
                    h[7] = key;
#pragma unroll
                    for (int m = 7; m > 0; m--)
                        if (h[m] < h[m - 1]) { ull t = h[m]; h[m] = h[m - 1]; h[m - 1] = t; }
                }
            }
        }
        unsigned hi = (unsigned)(h[0] >> 32);
        unsigned lo = (unsigned)h[0];
        unsigned hi_min = __reduce_min_sync(0xffffffffu, hi);
        unsigned lo_c = (hi == hi_min) ? lo : 0xffffffffu;
        unsigned lo_min = __reduce_min_sync(0xffffffffu, lo_c);
        ull mn = ((ull)hi_min << 32) | lo_min;
        if (h[0] == mn) {
            mylast = mn;
#pragma unroll
            for (int m = 0; m < 7; m++) h[m] = h[m + 1];
            h[7] = SENTK;
            g_knn_idx[i * K + r] = (int)lo_min;
            float ssq = __uint_as_float(hi_min);
            g_knn_d[i * K + r] = sqrtf(ssq + 1e-6f);
        }
    }
}

// ---------------- features: phase A + mma phase B + LN ----------------
// float offsets
#define F_SE    0        // 48*132 = 6336
#define F_SML   6336     // 48*32  = 1536 fp32 small
#define F_SA    7872     // 128
#define F_SJ    8000     // 48 (int)
#define F_SD    8048     // 48
#define F_WPOS  8096     // 1056
#define F_BPOS  9152     // 16
#define F_GM    9168     // 384
#define F_P     9552     // 48 (int)
#define F_AA    9600     // 48 (int)
#define F_SMH   9648     // bf16 hi tile 48x40 -> 960 floats
#define F_SML2  10608    // bf16 lo tile -> 960 floats
#define F_TOT_F 11568
#define F_TOT_B (F_TOT_F * 4)   // 46272
#define SMH_OB  (F_SMH * 4)     // 38592
#define SML2_OB (F_SML2 * 4)    // 42432

__global__ void __launch_bounds__(128, 4) features_kernel(const float* __restrict__ X,
                                                          const float* __restrict__ Wpos,
                                                          const float* __restrict__ bpos,
                                                          const int* __restrict__ aatype,
                                                          const int* __restrict__ resi) {
    extern __shared__ float sm[];
    uint32_t sb = smem_u32(sm);
    float* sE     = sm + F_SE;
    float* sSmall = sm + F_SML;
    float* sA     = sm + F_SA;
    int*   sJ     = (int*)(sm + F_SJ);
    float* sD     = sm + F_SD;
    float* sWpos  = sm + F_WPOS;
    float* sbpos  = sm + F_BPOS;
    float* sGm    = sm + F_GM;
    int*   sP     = (int*)(sm + F_P);
    int*   sAA    = (int*)(sm + F_AA);

    int tid = threadIdx.x;
    int wid = tid >> 5, lane = tid & 31;
    int i = blockIdx.x;

    if (tid < 32) ((float4*)sA)[tid] = ((const float4*)(g_A + (size_t)i * 128))[tid];
    if (tid < K) { sJ[tid] = g_knn_idx[i * K + tid]; sD[tid] = g_knn_d[i * K + tid]; }
    for (int n = tid; n < 1056; n += 128) sWpos[n] = __ldg(Wpos + n);
    if (tid >= 64 && tid < 80) sbpos[tid - 64] = __ldg(bpos + tid - 64);
    __syncthreads();

    // Phase A1: transcendentals
    if (tid < K) {
        int k = tid;
        int j = sJ[k];
        float d = sD[k];
#pragma unroll
        for (int q = 0; q < 16; q++) {
            float mu = 2.0f + (20.0f / 15.0f) * (float)q;
            float t = (d - mu) * 0.8f;
            sSmall[k * 32 + 16 + q] = expf(-t * t);
        }
        sGm[k * 8 + 0] = d * 0.1f;
        sGm[k * 8 + 1] = 1.0f / (1.0f + d);
        sGm[k * 8 + 2] = expf(-d);
        sGm[k * 8 + 3] = sinf(d);
        sGm[k * 8 + 4] = cosf(d);
        float inv = 1.0f / (d + 1e-6f);
        float xs = X[3 * i], ys = X[3 * i + 1], zs = X[3 * i + 2];
        sGm[k * 8 + 5] = (X[3 * j] - xs) * inv;
        sGm[k * 8 + 6] = (X[3 * j + 1] - ys) * inv;
        sGm[k * 8 + 7] = (X[3 * j + 2] - zs) * inv;
        int off = resi[j] - resi[i];
        sP[k] = min(max(off + 8, 0), 15);
        sAA[k] = aatype[j];
    }
    __syncthreads();

    // Phase A2: e_pos dot products (768 units over 128 threads)
#pragma unroll
    for (int it = 0; it < 6; it++) {
        int u = it * 128 + tid;
        int k = u >> 4, r = u & 15;
        const float* wr = sWpos + r * 66;
        float acc = sbpos[r] + wr[sP[k]] + wr[40 + sAA[k]];
        const float* rb = sSmall + k * 32 + 16;
#pragma unroll
        for (int q = 0; q < 16; q++) acc = fmaf(rb[q], wr[16 + q], acc);
        const float* gm = sGm + k * 8;
#pragma unroll
        for (int g = 0; g < 8; g++) acc = fmaf(gm[g], wr[32 + g], acc);
        sSmall[k * 32 + r] = acc;
    }
    __syncthreads();

    // Convert Small to bf16 hi/lo ldmatrix tiles (48x40 stride)
#pragma unroll
    for (int it = 0; it < 12; it++) {
        int u = it * 128 + tid;
        int k = u >> 5, q = u & 31;
        __nv_bfloat16 h, l;
        bf16split(sSmall[k * 32 + q], h, l);
        ((__nv_bfloat16*)((char*)sm + SMH_OB))[k * 40 + q] = h;
        ((__nv_bfloat16*)((char*)sm + SML2_OB))[k * 40 + q] = l;
    }
    __syncthreads();

    // Phase B: mma (M=48, N=32 per warp, K=32) 3-term split + fixup
    {
        int g = lane >> 3, ri = lane & 7;
        uint32_t aoffS[3];
#pragma unroll
        for (int mf = 0; mf < 3; mf++)
            aoffS[mf] = (uint32_t)((mf * 16 + ri + (g & 1) * 8) * 40 + (g >> 1) * 8) * 2;

        float acc[3][4][4];
#pragma unroll
        for (int mf = 0; mf < 3; mf++)
#pragma unroll
            for (int nf = 0; nf < 4; nf++)
#pragma unroll
                for (int q = 0; q < 4; q++) acc[mf][nf][q] = 0.f;

#pragma unroll
        for (int ks = 0; ks < 2; ks++) {
            uint32_t kb = ks * 32;
            uint32_t ah[3][4], al[3][4];
#pragma unroll
            for (int mf = 0; mf < 3; mf++) {
                ldm4(ah[mf], sb + SMH_OB + aoffS[mf] + kb);
                ldm4(al[mf], sb + SML2_OB + aoffS[mf] + kb);
            }
            uint32_t bh[2][4], bl[2][4];
#pragma unroll
            for (int nb = 0; nb < 2; nb++) {
                uint4 q0 = __ldg(&g_WsmFrag[(((wid * 2 + ks) * 2 + nb) * 2 + 0) * 32 + lane]);
                uint4 q1 = __ldg(&g_WsmFrag[(((wid * 2 + ks) * 2 + nb) * 2 + 1) * 32 + lane]);
                bh[nb][0] = q0.x; bh[nb][1] = q0.y; bh[nb][2] = q0.z; bh[nb][3] = q0.w;
                bl[nb][0] = q1.x; bl[nb][1] = q1.y; bl[nb][2] = q1.z; bl[nb][3] = q1.w;
            }
#pragma unroll
            for (int mf = 0; mf < 3; mf++) {
#pragma unroll
                for (int nf = 0; nf < 4; nf++) {
                    const uint32_t* bhp = &bh[nf >> 1][(nf & 1) * 2];
                    const uint32_t* blp = &bl[nf >> 1][(nf & 1) * 2];
                    mma_bf16(acc[mf][nf], ah[mf], bhp);
                    mma_bf16(acc[mf][nf], ah[mf], blp);
                    mma_bf16(acc[mf][nf], al[mf], bhp);
                }
            }
        }

        // fixup + store: e = acc + A[col] + B[j[row]][col]
        size_t ebase = (size_t)i * K * 128;
#pragma unroll
        for (int mf = 0; mf < 3; mf++) {
            int r0 = mf * 16 + (lane >> 2);
            int r1 = r0 + 8;
            int j0 = sJ[r0], j1 = sJ[r1];
#pragma unroll
            for (int nf = 0; nf < 4; nf++) {
                int col = wid * 32 + nf * 8 + (lane & 3) * 2;
                float2 av = *(const float2*)(sA + col);
                float2 b0 = __ldg((const float2*)(g_B + (size_t)j0 * 128 + col));
                float2 b1 = __ldg((const float2*)(g_B + (size_t)j1 * 128 + col));
                float e00 = acc[mf][nf][0] + av.x + b0.x;
                float e01 = acc[mf][nf][1] + av.y + b0.y;
                float e10 = acc[mf][nf][2] + av.x + b1.x;
                float e11 = acc[mf][nf][3] + av.y + b1.y;
                sE[r0 * 132 + col] = e00; sE[r0 * 132 + col + 1] = e01;
                sE[r1 * 132 + col] = e10; sE[r1 * 132 + col + 1] = e11;
                __nv_bfloat16 h, l;
                __nv_bfloat162 hh, ll;
                bf16split(e00, h, l); hh.x = h; ll.x = l;
                bf16split(e01, h, l); hh.y = h; ll.y = l;
                *(__nv_bfloat162*)(g_Ehi + ebase + (size_t)r0 * 128 + col) = hh;
                *(__nv_bfloat162*)(g_Elo + ebase + (size_t)r0 * 128 + col) = ll;
                bf16split(e10, h, l); hh.x = h; ll.x = l;
                bf16split(e11, h, l); hh.y = h; ll.y = l;
                *(__nv_bfloat162*)(g_Ehi + ebase + (size_t)r1 * 128 + col) = hh;
                *(__nv_bfloat162*)(g_Elo + ebase + (size_t)r1 * 128 + col) = ll;
            }
        }
    }
    __syncthreads();

    // LN stats (fp32)
    {
        for (int k = wid; k < K; k += 4) {
            float s = 0.f, ss = 0.f;
#pragma unroll
            for (int q = 0; q < 4; q++) {
                float v = sE[k * 132 + lane + q * 32];
                s += v;
                ss = fmaf(v, v, ss);
            }
#pragma unroll
            for (int off = 16; off > 0; off >>= 1) {
                s += __shfl_xor_sync(0xffffffffu, s, off);
                ss += __shfl_xor_sync(0xffffffffu, ss, off);
            }
            if (lane == 0) {
                float mean = s * (1.0f / 128.0f);
                float var = ss * (1.0f / 128.0f) - mean * mean;
                g_mean[i * K + k] = mean;
                g_rstd[i * K + k] = rsqrtf(var + 1e-5f);
            }
        }
    }
}

// ---------------- projection GEMM: E in smem, W frags from global ----------------
#define SSTR 136
#define EHI_OFF 0
#define ELO_OFF (128 * SSTR * 2)          // 34816
#define GEMM_SMEM (2 * 128 * SSTR * 2)    // 69632

__global__ void __launch_bounds__(256, 3) proj_gemm_kernel(float* __restrict__ out) {
    extern __shared__ __align__(16) char gsm[];
    uint32_t sb = smem_u32(gsm);
    int tid = threadIdx.x;
    int wid = tid >> 5, lane = tid & 31;
    int m0 = blockIdx.x * 128;

    // ---- stage E hi/lo ----
#pragma unroll
    for (int it = 0; it < 8; it++) {
        int vec = it * 256 + tid;
        int r = vec >> 4;
        int c8 = (vec & 15) << 3;
        uint32_t so = (uint32_t)r * (SSTR * 2) + c8 * 2;
        *(uint4*)(gsm + EHI_OFF + so) = __ldg((const uint4*)(g_Ehi + ((size_t)(m0 + r) << 7) + c8));
        *(uint4*)(gsm + ELO_OFF + so) = __ldg((const uint4*)(g_Elo + ((size_t)(m0 + r) << 7) + c8));
    }
    __syncthreads();

    int m_base = (wid >> 2) * 64;
    int nsl = wid & 3;
    int n_base = nsl * 32;
    int g = lane >> 3, ri = lane & 7;

    uint32_t aoff[4];
#pragma unroll
    for (int mf = 0; mf < 4; mf++)
        aoff[mf] = (uint32_t)((m_base + mf * 16 + ri + (g & 1) * 8) * SSTR + (g >> 1) * 8) * 2;

    float acc[4][4][4];
#pragma unroll
    for (int mf = 0; mf < 4; mf++)
#pragma unroll
        for (int nf = 0; nf < 4; nf++)
#pragma unroll
            for (int q = 0; q < 4; q++) acc[mf][nf][q] = 0.f;

#pragma unroll
    for (int ks = 0; ks < 8; ks++) {
        uint32_t kb = ks * 32;
        uint32_t ah[4][4], al[4][4], bh[2][4], bl[2][4];
#pragma unroll
        for (int mf = 0; mf < 4; mf++) {
            ldm4(ah[mf], sb + EHI_OFF + aoff[mf] + kb);
            ldm4(al[mf], sb + ELO_OFF + aoff[mf] + kb);
        }
#pragma unroll
        for (int nb = 0; nb < 2; nb++) {
            uint4 q0 = __ldg(&g_WpFrag[(((nsl * 8 + ks) * 2 + nb) * 2 + 0) * 32 + lane]);
            uint4 q1 = __ldg(&g_WpFrag[(((nsl * 8 + ks) * 2 + nb) * 2 + 1) * 32 + lane]);
            bh[nb][0] = q0.x; bh[nb][1] = q0.y; bh[nb][2] = q0.z; bh[nb][3] = q0.w;
            bl[nb][0] = q1.x; bl[nb][1] = q1.y; bl[nb][2] = q1.z; bl[nb][3] = q1.w;
        }
#pragma unroll
        for (int mf = 0; mf < 4; mf++) {
#pragma unroll
            for (int nf = 0; nf < 4; nf++) {
                const uint32_t* bhp = &bh[nf >> 1][(nf & 1) * 2];
                const uint32_t* blp = &bl[nf >> 1][(nf & 1) * 2];
                mma_bf16(acc[mf][nf], ah[mf], bhp);
                mma_bf16(acc[mf][nf], ah[mf], blp);
                mma_bf16(acc[mf][nf], al[mf], bhp);
            }
        }
    }

    // ---- epilogue ----
#pragma unroll
    for (int mf = 0; mf < 4; mf++) {
        int r0 = m0 + m_base + mf * 16 + (lane >> 2);
        float mean0 = __ldg(g_mean + r0), rstd0 = __ldg(g_rstd + r0);
        float mean1 = __ldg(g_mean + r0 + 8), rstd1 = __ldg(g_rstd + r0 + 8);
#pragma unroll
        for (int nf = 0; nf < 4; nf++) {
            int col = n_base + nf * 8 + (lane & 3) * 2;
            float2 w1v = *(const float2*)(g_w1 + col);
            float2 c0v = *(const float2*)(g_c0 + col);
            float2 o0, o1;
            o0.x = fmaf(rstd0, acc[mf][nf][0] - mean0 * w1v.x, c0v.x);
            o0.y = fmaf(rstd0, acc[mf][nf][1] - mean0 * w1v.y, c0v.y);
            o1.x = fmaf(rstd1, acc[mf][nf][2] - mean1 * w1v.x, c0v.x);
            o1.y = fmaf(rstd1, acc[mf][nf][3] - mean1 * w1v.y, c0v.y);
            *(float2*)(out + (size_t)r0 * 128 + col) = o0;
            *(float2*)(out + (size_t)(r0 + 8) * 128 + col) = o1;
        }
    }
}

// ---------------- launch ----------------
extern "C" void kernel_launch(void* const* d_in, const int* in_sizes, int n_in,
                              void* d_out, int out_size) {
    const float* X        = (const float*)d_in[0];
    const float* node_h   = (const float*)d_in[1];
    const float* f_node   = (const float*)d_in[2];
    const float* Wpos     = (const float*)d_in[3];
    const float* bpos     = (const float*)d_in[4];
    const float* We       = (const float*)d_in[5];
    const float* ln_scale = (const float*)d_in[6];
    const float* ln_bias  = (const float*)d_in[7];
    const float* Wproj    = (const float*)d_in[8];
    const float* bproj    = (const float*)d_in[9];
    const int*   aatype   = (const int*)d_in[10];
    const int*   resi     = (const int*)d_in[11];
    float* out = (float*)d_out;

    cudaFuncSetAttribute(knn_kernel, cudaFuncAttributeMaxDynamicSharedMemorySize, 3 * L * 4);
    cudaFuncSetAttribute(features_kernel, cudaFuncAttributeMaxDynamicSharedMemorySize, F_TOT_B);
    cudaFuncSetAttribute(proj_gemm_kernel, cudaFuncAttributeMaxDynamicSharedMemorySize, GEMM_SMEM);
    cudaFuncSetAttribute(prep_frag_kernel, cudaFuncAttributeMaxDynamicSharedMemorySize, PF_TOT);

    prep_small_kernel<<<32, 256>>>(Wproj, ln_scale, ln_bias, bproj, We);
    prep_frag_kernel<<<1, 256, PF_TOT>>>(Wproj, ln_scale, We);
    prep_ab_kernel<<<L / 32, 128>>>(node_h, f_node);
    knn_kernel<<<L / 16, 512, 3 * L * 4>>>(X);
    features_kernel<<<L, 128, F_TOT_B>>>(X, Wpos, bpos, aatype, resi);
    proj_gemm_kernel<<<N_TILES, 256, GEMM_SMEM>>>(out);
}

// round 14
// speedup vs baseline: 1.1978x; 1.1978x over previous
#include <cuda_runtime.h>
#include <cuda_bf16.h>
#include <cstdint>
#include <math.h>

#define L 8192
#define K 48
#define SENTK 0xFFFFFFFFFFFFFFFFULL
typedef unsigned long long ull;

#define M_EDGES (L * K)          // 393216
#define N_TILES2 (M_EDGES / 256) // 1536

// ---------------- device scratch (static; allocation-free) ----------------
__device__ __align__(16) float g_A[L * 128];
__device__ __align__(16) float g_B[L * 128];
__device__ __align__(16) ull   g_Wsm2P[16 * 128];
__device__ __align__(16) float g_WAT[128 * 128];
__device__ __align__(16) float g_WfT[128 * 128];
__device__ __align__(16) float g_WhT[128 * 128];
__device__ __align__(16) float g_w1[128];
__device__ __align__(16) float g_c0[128];
__device__ __align__(16) __nv_bfloat16 g_WT_hi[128 * 128];
__device__ __align__(16) __nv_bfloat16 g_WT_lo[128 * 128];
__device__ int   g_knn_idx[L * K];
__device__ float g_knn_d[L * K];
__device__ __align__(16) __nv_bfloat16 g_Ehi[(size_t)M_EDGES * 128];
__device__ __align__(16) __nv_bfloat16 g_Elo[(size_t)M_EDGES * 128];
__device__ float g_mean[M_EDGES];
__device__ float g_rstd[M_EDGES];

// ---------------- helpers ----------------
__device__ __forceinline__ ull fma2(ull a, ull b, ull c) {
    ull d;
    asm("fma.rn.f32x2 %0, %1, %2, %3;" : "=l"(d) : "l"(a), "l"(b), "l"(c));
    return d;
}
__device__ __forceinline__ ull pack2(float lo, float hi) {
    ull d;
    asm("mov.b64 %0, {%1, %2};" : "=l"(d) : "r"(__float_as_uint(lo)), "r"(__float_as_uint(hi)));
    return d;
}
__device__ __forceinline__ float lo2(ull v) { return __uint_as_float((unsigned)v); }
__device__ __forceinline__ float hi2(ull v) { return __uint_as_float((unsigned)(v >> 32)); }

__device__ __forceinline__ uint32_t smem_u32(const void* p) {
    uint32_t a;
    asm("{ .reg .u64 t; cvta.to.shared.u64 t, %1; cvt.u32.u64 %0, t; }" : "=r"(a) : "l"(p));
    return a;
}
__device__ __forceinline__ void ldm4(uint32_t* r, uint32_t addr) {
    asm volatile("ldmatrix.sync.aligned.m8n8.x4.shared.b16 {%0,%1,%2,%3}, [%4];"
                 : "=r"(r[0]), "=r"(r[1]), "=r"(r[2]), "=r"(r[3]) : "r"(addr));
}
__device__ __forceinline__ void mma_bf16(float* c, const uint32_t* a, const uint32_t* b) {
    asm volatile("mma.sync.aligned.m16n8k16.row.col.f32.bf16.bf16.f32 "
                 "{%0,%1,%2,%3}, {%4,%5,%6,%7}, {%8,%9}, {%0,%1,%2,%3};"
                 : "+f"(c[0]), "+f"(c[1]), "+f"(c[2]), "+f"(c[3])
                 : "r"(a[0]), "r"(a[1]), "r"(a[2]), "r"(a[3]), "r"(b[0]), "r"(b[1]));
}

// exact R11 ssq chain
__device__ __forceinline__ float ssq_exact(float xi, float yi, float zi,
                                           float x, float y, float z) {
    float dx = xi - x, dy = yi - y, dz = zi - z;
    return __fadd_rn(__fadd_rn(__fmul_rn(dx, dx), __fmul_rn(dy, dy)), __fmul_rn(dz, dz));
}

// ---------------- tiny precompute ----------------
__global__ void prep_small_kernel(const float* __restrict__ Wproj,
                                  const float* __restrict__ ln_scale,
                                  const float* __restrict__ ln_bias,
                                  const float* __restrict__ bproj,
                                  const float* __restrict__ We) {
    int gid = blockIdx.x * blockDim.x + threadIdx.x;
    int NT = gridDim.x * blockDim.x;
    for (int n = gid; n < 16384; n += NT) {
        int c = n >> 7, t = n & 127;
        g_WAT[n] = We[t * 416 + 160 + c];
        g_WfT[n] = We[t * 416 + c];
        g_WhT[n] = We[t * 416 + 288 + c];
        int tt = n >> 7, cc = n & 127;
        float w = Wproj[tt * 128 + cc] * ln_scale[cc];
        __nv_bfloat16 h = __float2bfloat16(w);
        float res = w - __bfloat162float(h);
        g_WT_hi[n] = h;
        g_WT_lo[n] = __float2bfloat16(res);
    }
    for (int n = gid; n < 2048; n += NT) {
        int q2 = n >> 7, c = n & 127;
        g_Wsm2P[n] = pack2(We[c * 416 + 128 + 2 * q2], We[c * 416 + 128 + 2 * q2 + 1]);
    }
    if (gid < 128) {
        float s1 = 0.f, s0 = 0.f;
        for (int c = 0; c < 128; c++) {
            float w = Wproj[gid * 128 + c];
            s1 += w * ln_scale[c];
            s0 += w * ln_bias[c];
        }
        g_w1[gid] = s1;
        g_c0[gid] = s0 + bproj[gid];
    }
}

// ---------------- A/B tables ----------------
__global__ void __launch_bounds__(128) prep_ab_kernel(const float* __restrict__ node_h,
                                                      const float* __restrict__ f_node) {
    __shared__ float nh[32 * 128];
    __shared__ float fn[32 * 128];
    int tid = threadIdx.x;
    int i0 = blockIdx.x * 32;
    for (int f = tid; f < 32 * 128; f += 128) {
        nh[f] = node_h[i0 * 128 + f];
        fn[f] = f_node[i0 * 128 + f];
    }
    __syncthreads();
    for (int ch = 0; ch < 4; ch++) {
        float a[8], b[8];
#pragma unroll
        for (int ii = 0; ii < 8; ii++) { a[ii] = 0.f; b[ii] = 0.f; }
#pragma unroll 4
        for (int c = 0; c < 128; c++) {
            float wa = __ldg(g_WAT + c * 128 + tid);
            float wf = __ldg(g_WfT + c * 128 + tid);
            float wh = __ldg(g_WhT + c * 128 + tid);
#pragma unroll
            for (int ii = 0; ii < 8; ii++) {
                int row = ch * 8 + ii;
                float n = nh[row * 128 + c];
                float f = fn[row * 128 + c];
                a[ii] = fmaf(n, wa, a[ii]);
                b[ii] = fmaf(f, wf, fmaf(n, wh, b[ii]));
            }
        }
#pragma unroll
        for (int ii = 0; ii < 8; ii++) {
            g_A[(i0 + ch * 8 + ii) * 128 + tid] = a[ii];
            g_B[(i0 + ch * 8 + ii) * 128 + tid] = b[ii];
        }
    }
}

// ---------------- KNN: paired LDS.64, exact scalar ssq, REDUX rounds ----------------
__global__ void __launch_bounds__(512) knn_kernel(const float* __restrict__ X) {
    extern __shared__ float sx[];   // [x:L][y:L][z:L]
    int tid = threadIdx.x;
    for (int idx = tid; idx < L; idx += 512) {
        sx[idx]         = X[3 * idx];
        sx[L + idx]     = X[3 * idx + 1];
        sx[2 * L + idx] = X[3 * idx + 2];
    }
    __syncthreads();
    int lane = tid & 31;
    int i = blockIdx.x * 16 + (tid >> 5);
    float xi = sx[i], yi = sx[L + i], zi = sx[2 * L + i];

    ull h[8];
#pragma unroll
    for (int m = 0; m < 8; m++) h[m] = SENTK;

    const ull* px = (const ull*)sx;
    const ull* py = (const ull*)(sx + L);
    const ull* pz = (const ull*)(sx + 2 * L);

    // initial scan: 2 candidates per iteration via LDS.64, exact scalar math
#pragma unroll 4
    for (int s = 0; s < L / 64; s++) {
        int u = lane + (s << 5);
        ull xw = px[u], yw = py[u], zw = pz[u];
        float s0 = ssq_exact(xi, yi, zi, lo2(xw), lo2(yw), lo2(zw));
        float s1 = ssq_exact(xi, yi, zi, hi2(xw), hi2(yw), hi2(zw));
        ull key0 = ((ull)__float_as_uint(s0) << 32) | (unsigned)(2 * u);
        ull key1 = ((ull)__float_as_uint(s1) << 32) | (unsigned)(2 * u + 1);
        if (key0 < h[7]) {
            h[7] = key0;
#pragma unroll
            for (int m = 7; m > 0; m--)
                if (h[m] < h[m - 1]) { ull t = h[m]; h[m] = h[m - 1]; h[m - 1] = t; }
        }
        if (key1 < h[7]) {
            h[7] = key1;
#pragma unroll
            for (int m = 7; m > 0; m--)
                if (h[m] < h[m - 1]) { ull t = h[m]; h[m] = h[m - 1]; h[m - 1] = t; }
        }
    }

    ull mylast = 0ULL;
    for (int r = 0; r < K; r++) {
        if (h[0] == SENTK) {   // rare refill: rescan lane's partition, keys > mylast
            for (int s = 0; s < L / 64; s++) {
                int u = lane + (s << 5);
                ull xw = px[u], yw = py[u], zw = pz[u];
                float s0 = ssq_exact(xi, yi, zi, lo2(xw), lo2(yw), lo2(zw));
                float s1 = ssq_exact(xi, yi, zi, hi2(xw), hi2(yw), hi2(zw));
                ull key0 = ((ull)__float_as_uint(s0) << 32) | (unsigned)(2 * u);
                ull key1 = ((ull)__float_as_uint(s1) << 32) | (unsigned)(2 * u + 1);
                if (key0 > mylast && key0 < h[7]) {
                    h[7] = key0;
#pragma unroll
                    for (int m = 7; m > 0; m--)
                        if (h[m] < h[m - 1]) { ull t = h[m]; h[m] = h[m - 1]; h[m - 1] = t; }
                }
                if (key1 > mylast && key1 < h[7]) {
                    h[7] = key1;
#pragma unroll
                    for (int m = 7; m > 0; m--)
                        if (h[m] < h[m - 1]) { ull t = h[m]; h[m] = h[m - 1]; h[m - 1] = t; }
                }
            }
        }
        unsigned hi = (unsigned)(h[0] >> 32);
        unsigned lo = (unsigned)h[0];
        unsigned hi_min = __reduce_min_sync(0xffffffffu, hi);
        unsigned lo_c = (hi == hi_min) ? lo : 0xffffffffu;
        unsigned lo_min = __reduce_min_sync(0xffffffffu, lo_c);
        ull mn = ((ull)hi_min << 32) | lo_min;
        if (h[0] == mn) {
            mylast = mn;
#pragma unroll
            for (int m = 0; m < 7; m++) h[m] = h[m + 1];
            h[7] = SENTK;
            g_knn_idx[i * K + r] = (int)lo_min;
            float ssq = __uint_as_float(hi_min);
            g_knn_d[i * K + r] = sqrtf(ssq + 1e-6f);
        }
    }
}

// ---------------- features: smem-parallel phase A + phases B/LN (R11) ----------------
#define F_SE    0        // 48*132 = 6336
#define F_SML   6336     // 48*32  = 1536
#define F_SA    7872     // 128
#define F_SJ    8000     // 48 (int)
#define F_SD    8048     // 48
#define F_WPOS  8096     // 1056
#define F_BPOS  9152     // 16
#define F_GM    9168     // 384
#define F_P     9552     // 48 (int)
#define F_AA    9600     // 48 (int)
#define F_TOT_B 38592    // 9648 floats

__global__ void __launch_bounds__(128, 4) features_kernel(const float* __restrict__ X,
                                                          const float* __restrict__ Wpos,
                                                          const float* __restrict__ bpos,
                                                          const int* __restrict__ aatype,
                                                          const int* __restrict__ resi) {
    extern __shared__ float sm[];
    float* sE     = sm + F_SE;
    float* sSmall = sm + F_SML;
    float* sA     = sm + F_SA;
    int*   sJ     = (int*)(sm + F_SJ);
    float* sD     = sm + F_SD;
    float* sWpos  = sm + F_WPOS;
    float* sbpos  = sm + F_BPOS;
    float* sGm    = sm + F_GM;
    int*   sP     = (int*)(sm + F_P);
    int*   sAA    = (int*)(sm + F_AA);

    int tid = threadIdx.x;
    int i = blockIdx.x;

    if (tid < 32) ((float4*)sA)[tid] = ((const float4*)(g_A + (size_t)i * 128))[tid];
    if (tid < K) { sJ[tid] = g_knn_idx[i * K + tid]; sD[tid] = g_knn_d[i * K + tid]; }
    for (int n = tid; n < 1056; n += 128) sWpos[n] = __ldg(Wpos + n);
    if (tid >= 64 && tid < 80) sbpos[tid - 64] = __ldg(bpos + tid - 64);
    __syncthreads();

    if (tid < K) {
        int k = tid;
        int j = sJ[k];
        float d = sD[k];
#pragma unroll
        for (int q = 0; q < 16; q++) {
            float mu = 2.0f + (20.0f / 15.0f) * (float)q;
            float t = (d - mu) * 0.8f;
            sSmall[k * 32 + 16 + q] = expf(-t * t);
        }
        sGm[k * 8 + 0] = d * 0.1f;
        sGm[k * 8 + 1] = 1.0f / (1.0f + d);
        sGm[k * 8 + 2] = expf(-d);
        sGm[k * 8 + 3] = sinf(d);
        sGm[k * 8 + 4] = cosf(d);
        float inv = 1.0f / (d + 1e-6f);
        float xs = X[3 * i], ys = X[3 * i + 1], zs = X[3 * i + 2];
        sGm[k * 8 + 5] = (X[3 * j] - xs) * inv;
        sGm[k * 8 + 6] = (X[3 * j + 1] - ys) * inv;
        sGm[k * 8 + 7] = (X[3 * j + 2] - zs) * inv;
        int off = resi[j] - resi[i];
        sP[k] = min(max(off + 8, 0), 15);
        sAA[k] = aatype[j];
    }
    __syncthreads();

#pragma unroll
    for (int it = 0; it < 6; it++) {
        int u = it * 128 + tid;
        int k = u >> 4, r = u & 15;
        const float* wr = sWpos + r * 66;
        float acc = sbpos[r] + wr[sP[k]] + wr[40 + sAA[k]];
        const float* rb = sSmall + k * 32 + 16;
#pragma unroll
        for (int q = 0; q < 16; q++) acc = fmaf(rb[q], wr[16 + q], acc);
        const float* gm = sGm + k * 8;
#pragma unroll
        for (int g = 0; g < 8; g++) acc = fmaf(gm[g], wr[32 + g], acc);
        sSmall[k * 32 + r] = acc;
    }
    __syncthreads();

    {
        int c = tid;
        ull w2[16];
#pragma unroll
        for (int q2 = 0; q2 < 16; q2++) w2[q2] = __ldg(g_Wsm2P + q2 * 128 + c);
        float a = sA[c];
        size_t ebase = (size_t)i * K * 128;
        for (int k0 = 0; k0 < K; k0 += 4) {
            ull acc[4];
#pragma unroll
            for (int kk = 0; kk < 4; kk++)
                acc[kk] = pack2(a + __ldg(g_B + (size_t)sJ[k0 + kk] * 128 + c), 0.f);
#pragma unroll
            for (int q2 = 0; q2 < 16; q2++) {
#pragma unroll
                for (int kk = 0; kk < 4; kk++) {
                    ull s2 = *(const ull*)(sSmall + (k0 + kk) * 32 + q2 * 2);
                    acc[kk] = fma2(s2, w2[q2], acc[kk]);
                }
            }
#pragma unroll
            for (int kk = 0; kk < 4; kk++) {
                float e = lo2(acc[kk]) + hi2(acc[kk]);
                sE[(k0 + kk) * 132 + c] = e;
                __nv_bfloat16 h = __float2bfloat16(e);
                __nv_bfloat16 l = __float2bfloat16(e - __bfloat162float(h));
                g_Ehi[ebase + (size_t)(k0 + kk) * 128 + c] = h;
                g_Elo[ebase + (size_t)(k0 + kk) * 128 + c] = l;
            }
        }
    }
    __syncthreads();

    {
        int wrp = tid >> 5, lane = tid & 31;
        for (int k = wrp; k < K; k += 4) {
            float s = 0.f, ss = 0.f;
#pragma unroll
            for (int q = 0; q < 4; q++) {
                float v = sE[k * 132 + lane + q * 32];
                s += v;
                ss = fmaf(v, v, ss);
            }
#pragma unroll
            for (int off = 16; off > 0; off >>= 1) {
                s += __shfl_xor_sync(0xffffffffu, s, off);
                ss += __shfl_xor_sync(0xffffffffu, ss, off);
            }
            if (lane == 0) {
                float mean = s * (1.0f / 128.0f);
                float var = ss * (1.0f / 128.0f) - mean * mean;
                g_mean[i * K + k] = mean;
                g_rstd[i * K + k] = rsqrtf(var + 1e-5f);
            }
        }
    }
}

// ---------------- projection GEMM: 256-row M-tile, two 128-row passes (R11) ----------------
#define SSTR 136
#define EHI_OFF 0
#define ELO_OFF (256 * SSTR * 2)           // 69632
#define WHI_OFF (2 * 256 * SSTR * 2)       // 139264
#define WLO_OFF (WHI_OFF + 128 * SSTR * 2) // 174080
#define GEMM_SMEM (WLO_OFF + 128 * SSTR * 2) // 208896

__global__ void __launch_bounds__(256, 1) proj_gemm_kernel(float* __restrict__ out) {
    extern __shared__ __align__(16) char gsm[];
    uint32_t sb = smem_u32(gsm);
    int tid = threadIdx.x;
    int wid = tid >> 5, lane = tid & 31;
    int m0 = blockIdx.x * 256;

#pragma unroll
    for (int it = 0; it < 8; it++) {
        int vec = it * 256 + tid;
        int n = vec >> 4;
        int c8 = (vec & 15) << 3;
        uint32_t so = (uint32_t)n * (SSTR * 2) + c8 * 2;
        *(uint4*)(gsm + WHI_OFF + so) = __ldg((const uint4*)(g_WT_hi + (size_t)n * 128 + c8));
        *(uint4*)(gsm + WLO_OFF + so) = __ldg((const uint4*)(g_WT_lo + (size_t)n * 128 + c8));
    }
#pragma unroll
    for (int it = 0; it < 16; it++) {
        int vec = it * 256 + tid;
        int r = vec >> 4;
        int c8 = (vec & 15) << 3;
        uint32_t so = (uint32_t)r * (SSTR * 2) + c8 * 2;
        *(uint4*)(gsm + EHI_OFF + so) = __ldg((const uint4*)(g_Ehi + ((size_t)(m0 + r) << 7) + c8));
        *(uint4*)(gsm + ELO_OFF + so) = __ldg((const uint4*)(g_Elo + ((size_t)(m0 + r) << 7) + c8));
    }
    __syncthreads();

    int g = lane >> 3, ri = lane & 7;
    int n_base = (wid & 3) * 32;
    uint32_t boff[2];
#pragma unroll
    for (int nb = 0; nb < 2; nb++)
        boff[nb] = (uint32_t)((n_base + nb * 16 + ri + (g >> 1) * 8) * SSTR + (g & 1) * 8) * 2;

#pragma unroll
    for (int half = 0; half < 2; half++) {
        int m_base = half * 128 + (wid >> 2) * 64;
        uint32_t aoff[4];
#pragma unroll
        for (int mf = 0; mf < 4; mf++)
            aoff[mf] = (uint32_t)((m_base + mf * 16 + ri + (g & 1) * 8) * SSTR + (g >> 1) * 8) * 2;

        float acc[4][4][4];
#pragma unroll
        for (int mf = 0; mf < 4; mf++)
#pragma unroll
            for (int nf = 0; nf < 4; nf++)
#pragma unroll
                for (int q = 0; q < 4; q++) acc[mf][nf][q] = 0.f;

#pragma unroll
        for (int ks = 0; ks < 8; ks++) {
            uint32_t kb = ks * 32;
            uint32_t ah[4][4], al[4][4], bh[2][4], bl[2][4];
#pragma unroll
            for (int mf = 0; mf < 4; mf++) {
                ldm4(ah[mf], sb + EHI_OFF + aoff[mf] + kb);
                ldm4(al[mf], sb + ELO_OFF + aoff[mf] + kb);
            }
#pragma unroll
            for (int nb = 0; nb < 2; nb++) {
                ldm4(bh[nb], sb + WHI_OFF + boff[nb] + kb);
                ldm4(bl[nb], sb + WLO_OFF + boff[nb] + kb);
            }
#pragma unroll
            for (int mf = 0; mf < 4; mf++) {
#pragma unroll
                for (int nf = 0; nf < 4; nf++) {
                    const uint32_t* bhp = &bh[nf >> 1][(nf & 1) * 2];
                    const uint32_t* blp = &bl[nf >> 1][(nf & 1) * 2];
                    mma_bf16(acc[mf][nf], ah[mf], bhp);
                    mma_bf16(acc[mf][nf], ah[mf], blp);
                    mma_bf16(acc[mf][nf], al[mf], bhp);
                }
            }
        }

#pragma unroll
        for (int mf = 0; mf < 4; mf++) {
            int r0 = m0 + m_base + mf * 16 + (lane >> 2);
            float mean0 = __ldg(g_mean + r0), rstd0 = __ldg(g_rstd + r0);
            float mean1 = __ldg(g_mean + r0 + 8), rstd1 = __ldg(g_rstd + r0 + 8);
#pragma unroll
            for (int nf = 0; nf < 4; nf++) {
                int col = n_base + nf * 8 + (lane & 3) * 2;
                float2 w1v = *(const float2*)(g_w1 + col);
                float2 c0v = *(const float2*)(g_c0 + col);
                float2 o0, o1;
                o0.x = fmaf(rstd0, acc[mf][nf][0] - mean0 * w1v.x, c0v.x);
                o0.y = fmaf(rstd0, acc[mf][nf][1] - mean0 * w1v.y, c0v.y);
                o1.x = fmaf(rstd1, acc[mf][nf][2] - mean1 * w1v.x, c0v.x);
                o1.y = fmaf(rstd1, acc[mf][nf][3] - mean1 * w1v.y, c0v.y);
                *(float2*)(out + (size_t)r0 * 128 + col) = o0;
                *(float2*)(out + (size_t)(r0 + 8) * 128 + col) = o1;
            }
        }
    }
}

// ---------------- launch ----------------
extern "C" void kernel_launch(void* const* d_in, const int* in_sizes, int n_in,
                              void* d_out, int out_size) {
    const float* X        = (const float*)d_in[0];
    const float* node_h   = (const float*)d_in[1];
    const float* f_node   = (const float*)d_in[2];
    const float* Wpos     = (const float*)d_in[3];
    const float* bpos     = (const float*)d_in[4];
    const float* We       = (const float*)d_in[5];
    const float* ln_scale = (const float*)d_in[6];
    const float* ln_bias  = (const float*)d_in[7];
    const float* Wproj    = (const float*)d_in[8];
    const float* bproj    = (const float*)d_in[9];
    const int*   aatype   = (const int*)d_in[10];
    const int*   resi     = (const int*)d_in[11];
    float* out = (float*)d_out;

    cudaFuncSetAttribute(knn_kernel, cudaFuncAttributeMaxDynamicSharedMemorySize, 3 * L * 4);
    cudaFuncSetAttribute(features_kernel, cudaFuncAttributeMaxDynamicSharedMemorySize, F_TOT_B);
    cudaFuncSetAttribute(proj_gemm_kernel, cudaFuncAttributeMaxDynamicSharedMemorySize, GEMM_SMEM);

    prep_small_kernel<<<32, 256>>>(Wproj, ln_scale, ln_bias, bproj, We);
    prep_ab_kernel<<<L / 32, 128>>>(node_h, f_node);
    knn_kernel<<<L / 16, 512, 3 * L * 4>>>(X);
    features_kernel<<<L, 128, F_TOT_B>>>(X, Wpos, bpos, aatype, resi);
    proj_gemm_kernel<<<N_TILES2, 256, GEMM_SMEM>>>(out);
}

// round 15
// speedup vs baseline: 1.2169x; 1.0160x over previous
#include <cuda_runtime.h>
#include <cuda_bf16.h>
#include <cstdint>
#include <math.h>

#define L 8192
#define K 48
#define SENTK 0xFFFFFFFFFFFFFFFFULL
typedef unsigned long long ull;

#define M_EDGES (L * K)          // 393216
#define N_TILES2 (M_EDGES / 256) // 1536

// ---------------- device scratch (static; allocation-free) ----------------
__device__ __align__(16) float g_A[L * 128];
__device__ __align__(16) float g_B[L * 128];
__device__ __align__(16) ull   g_Wsm2P[16 * 128];
__device__ __align__(16) float g_WAT[128 * 128];
__device__ __align__(16) float g_WfT[128 * 128];
__device__ __align__(16) float g_WhT[128 * 128];
__device__ __align__(16) float g_w1[128];
__device__ __align__(16) float g_c0[128];
__device__ __align__(16) __nv_bfloat16 g_WT_hi[128 * 128];
__device__ __align__(16) __nv_bfloat16 g_WT_lo[128 * 128];
__device__ int   g_knn_idx[L * K];
__device__ float g_knn_d[L * K];
__device__ __align__(16) __nv_bfloat16 g_Ehi[(size_t)M_EDGES * 128];
__device__ __align__(16) __nv_bfloat16 g_Elo[(size_t)M_EDGES * 128];
__device__ float g_mean[M_EDGES];
__device__ float g_rstd[M_EDGES];

// ---------------- helpers ----------------
__device__ __forceinline__ ull fma2(ull a, ull b, ull c) {
    ull d;
    asm("fma.rn.f32x2 %0, %1, %2, %3;" : "=l"(d) : "l"(a), "l"(b), "l"(c));
    return d;
}
__device__ __forceinline__ ull pack2(float lo, float hi) {
    ull d;
    asm("mov.b64 %0, {%1, %2};" : "=l"(d) : "r"(__float_as_uint(lo)), "r"(__float_as_uint(hi)));
    return d;
}
__device__ __forceinline__ float lo2(ull v) { return __uint_as_float((unsigned)v); }
__device__ __forceinline__ float hi2(ull v) { return __uint_as_float((unsigned)(v >> 32)); }

__device__ __forceinline__ uint32_t smem_u32(const void* p) {
    uint32_t a;
    asm("{ .reg .u64 t; cvta.to.shared.u64 t, %1; cvt.u32.u64 %0, t; }" : "=r"(a) : "l"(p));
    return a;
}
__device__ __forceinline__ void ldm4(uint32_t* r, uint32_t addr) {
    asm volatile("ldmatrix.sync.aligned.m8n8.x4.shared.b16 {%0,%1,%2,%3}, [%4];"
                 : "=r"(r[0]), "=r"(r[1]), "=r"(r[2]), "=r"(r[3]) : "r"(addr));
}
__device__ __forceinline__ void mma_bf16(float* c, const uint32_t* a, const uint32_t* b) {
    asm volatile("mma.sync.aligned.m16n8k16.row.col.f32.bf16.bf16.f32 "
                 "{%0,%1,%2,%3}, {%4,%5,%6,%7}, {%8,%9}, {%0,%1,%2,%3};"
                 : "+f"(c[0]), "+f"(c[1]), "+f"(c[2]), "+f"(c[3])
                 : "r"(a[0]), "r"(a[1]), "r"(a[2]), "r"(a[3]), "r"(b[0]), "r"(b[1]));
}

// ---------------- tiny precompute ----------------
__global__ void prep_small_kernel(const float* __restrict__ Wproj,
                                  const float* __restrict__ ln_scale,
                                  const float* __restrict__ ln_bias,
                                  const float* __restrict__ bproj,
                                  const float* __restrict__ We) {
    int gid = blockIdx.x * blockDim.x + threadIdx.x;
    int NT = gridDim.x * blockDim.x;
    for (int n = gid; n < 16384; n += NT) {
        int c = n >> 7, t = n & 127;
        g_WAT[n] = We[t * 416 + 160 + c];
        g_WfT[n] = We[t * 416 + c];
        g_WhT[n] = We[t * 416 + 288 + c];
        int tt = n >> 7, cc = n & 127;
        float w = Wproj[tt * 128 + cc] * ln_scale[cc];
        __nv_bfloat16 h = __float2bfloat16(w);
        float res = w - __bfloat162float(h);
        g_WT_hi[n] = h;
        g_WT_lo[n] = __float2bfloat16(res);
    }
    for (int n = gid; n < 2048; n += NT) {
        int q2 = n >> 7, c = n & 127;
        g_Wsm2P[n] = pack2(We[c * 416 + 128 + 2 * q2], We[c * 416 + 128 + 2 * q2 + 1]);
    }
    if (gid < 128) {
        float s1 = 0.f, s0 = 0.f;
        for (int c = 0; c < 128; c++) {
            float w = Wproj[gid * 128 + c];
            s1 += w * ln_scale[c];
            s0 += w * ln_bias[c];
        }
        g_w1[gid] = s1;
        g_c0[gid] = s0 + bproj[gid];
    }
}

// ---------------- A/B tables ----------------
__global__ void __launch_bounds__(128) prep_ab_kernel(const float* __restrict__ node_h,
                                                      const float* __restrict__ f_node) {
    __shared__ float nh[32 * 128];
    __shared__ float fn[32 * 128];
    int tid = threadIdx.x;
    int i0 = blockIdx.x * 32;
    for (int f = tid; f < 32 * 128; f += 128) {
        nh[f] = node_h[i0 * 128 + f];
        fn[f] = f_node[i0 * 128 + f];
    }
    __syncthreads();
    for (int ch = 0; ch < 4; ch++) {
        float a[8], b[8];
#pragma unroll
        for (int ii = 0; ii < 8; ii++) { a[ii] = 0.f; b[ii] = 0.f; }
#pragma unroll 4
        for (int c = 0; c < 128; c++) {
            float wa = __ldg(g_WAT + c * 128 + tid);
            float wf = __ldg(g_WfT + c * 128 + tid);
            float wh = __ldg(g_WhT + c * 128 + tid);
#pragma unroll
            for (int ii = 0; ii < 8; ii++) {
                int row = ch * 8 + ii;
                float n = nh[row * 128 + c];
                float f = fn[row * 128 + c];
                a[ii] = fmaf(n, wa, a[ii]);
                b[ii] = fmaf(f, wf, fmaf(n, wh, b[ii]));
            }
        }
#pragma unroll
        for (int ii = 0; ii < 8; ii++) {
            g_A[(i0 + ch * 8 + ii) * 128 + tid] = a[ii];
            g_B[(i0 + ch * 8 + ii) * 128 + tid] = b[ii];
        }
    }
}

// ---------------- KNN: R11 exact (705us-config) ----------------
__global__ void __launch_bounds__(512) knn_kernel(const float* __restrict__ X) {
    extern __shared__ float sx[];
    int tid = threadIdx.x;
    for (int idx = tid; idx < L; idx += 512) {
        sx[idx]         = X[3 * idx];
        sx[L + idx]     = X[3 * idx + 1];
        sx[2 * L + idx] = X[3 * idx + 2];
    }
    __syncthreads();
    int lane = tid & 31;
    int i = blockIdx.x * 16 + (tid >> 5);
    float xi = sx[i], yi = sx[L + i], zi = sx[2 * L + i];

    ull h[8];
#pragma unroll
    for (int m = 0; m < 8; m++) h[m] = SENTK;

#pragma unroll 4
    for (int s = 0; s < L / 32; s++) {
        int j = lane + (s << 5);
        float dx = xi - sx[j], dy = yi - sx[L + j], dz = zi - sx[2 * L + j];
        float ssq = __fadd_rn(__fadd_rn(__fmul_rn(dx, dx), __fmul_rn(dy, dy)), __fmul_rn(dz, dz));
        unsigned sb = __float_as_uint(ssq);
        unsigned hs = (unsigned)(h[7] >> 32);
        if (sb < hs || (sb == hs && (unsigned)j < (unsigned)h[7])) {
            h[7] = ((ull)sb << 32) | (unsigned)j;
#pragma unroll
            for (int m = 7; m > 0; m--)
                if (h[m] < h[m - 1]) { ull t = h[m]; h[m] = h[m - 1]; h[m - 1] = t; }
        }
    }

    ull mylast = 0ULL;
    for (int r = 0; r < K; r++) {
        if (h[0] == SENTK) {
            for (int s = 0; s < L / 32; s++) {
                int j = lane + (s << 5);
                float dx = xi - sx[j], dy = yi - sx[L + j], dz = zi - sx[2 * L + j];
                float ssq = __fadd_rn(__fadd_rn(__fmul_rn(dx, dx), __fmul_rn(dy, dy)), __fmul_rn(dz, dz));
                ull key = ((ull)__float_as_uint(ssq) << 32) | (unsigned)j;
                if (key > mylast && key < h[7]) {
                    h[7] = key;
#pragma unroll
                    for (int m = 7; m > 0; m--)
                        if (h[m] < h[m - 1]) { ull t = h[m]; h[m] = h[m - 1]; h[m - 1] = t; }
                }
            }
        }
        unsigned hi = (unsigned)(h[0] >> 32);
        unsigned lo = (unsigned)h[0];
        unsigned hi_min = __reduce_min_sync(0xffffffffu, hi);
        unsigned lo_c = (hi == hi_min) ? lo : 0xffffffffu;
        unsigned lo_min = __reduce_min_sync(0xffffffffu, lo_c);
        ull mn = ((ull)hi_min << 32) | lo_min;
        if (h[0] == mn) {
            mylast = mn;
#pragma unroll
            for (int m = 0; m < 7; m++) h[m] = h[m + 1];
            h[7] = SENTK;
            g_knn_idx[i * K + r] = (int)lo_min;
            float ssq = __uint_as_float(hi_min);
            g_knn_d[i * K + r] = sqrtf(ssq + 1e-6f);
        }
    }
}

// ---------------- features: R11 + LDS.128 phase-B s2 loads ----------------
#define F_SE    0        // 48*132 = 6336
#define F_SML   6336     // 48*32  = 1536
#define F_SA    7872     // 128
#define F_SJ    8000     // 48 (int)
#define F_SD    8048     // 48
#define F_WPOS  8096     // 1056
#define F_BPOS  9152     // 16
#define F_GM    9168     // 384
#define F_P     9552     // 48 (int)
#define F_AA    9600     // 48 (int)
#define F_TOT_B 38592    // 9648 floats

__global__ void __launch_bounds__(128, 4) features_kernel(const float* __restrict__ X,
                                                          const float* __restrict__ Wpos,
                                                          const float* __restrict__ bpos,
                                                          const int* __restrict__ aatype,
                                                          const int* __restrict__ resi) {
    extern __shared__ float sm[];
    float* sE     = sm + F_SE;
    float* sSmall = sm + F_SML;
    float* sA     = sm + F_SA;
    int*   sJ     = (int*)(sm + F_SJ);
    float* sD     = sm + F_SD;
    float* sWpos  = sm + F_WPOS;
    float* sbpos  = sm + F_BPOS;
    float* sGm    = sm + F_GM;
    int*   sP     = (int*)(sm + F_P);
    int*   sAA    = (int*)(sm + F_AA);

    int tid = threadIdx.x;
    int i = blockIdx.x;

    if (tid < 32) ((float4*)sA)[tid] = ((const float4*)(g_A + (size_t)i * 128))[tid];
    if (tid < K) { sJ[tid] = g_knn_idx[i * K + tid]; sD[tid] = g_knn_d[i * K + tid]; }
    for (int n = tid; n < 1056; n += 128) sWpos[n] = __ldg(Wpos + n);
    if (tid >= 64 && tid < 80) sbpos[tid - 64] = __ldg(bpos + tid - 64);
    __syncthreads();

    if (tid < K) {
        int k = tid;
        int j = sJ[k];
        float d = sD[k];
#pragma unroll
        for (int q = 0; q < 16; q++) {
            float mu = 2.0f + (20.0f / 15.0f) * (float)q;
            float t = (d - mu) * 0.8f;
            sSmall[k * 32 + 16 + q] = expf(-t * t);
        }
        sGm[k * 8 + 0] = d * 0.1f;
        sGm[k * 8 + 1] = 1.0f / (1.0f + d);
        sGm[k * 8 + 2] = expf(-d);
        sGm[k * 8 + 3] = sinf(d);
        sGm[k * 8 + 4] = cosf(d);
        float inv = 1.0f / (d + 1e-6f);
        float xs = X[3 * i], ys = X[3 * i + 1], zs = X[3 * i + 2];
        sGm[k * 8 + 5] = (X[3 * j] - xs) * inv;
        sGm[k * 8 + 6] = (X[3 * j + 1] - ys) * inv;
        sGm[k * 8 + 7] = (X[3 * j + 2] - zs) * inv;
        int off = resi[j] - resi[i];
        sP[k] = min(max(off + 8, 0), 15);
        sAA[k] = aatype[j];
    }
    __syncthreads();

#pragma unroll
    for (int it = 0; it < 6; it++) {
        int u = it * 128 + tid;
        int k = u >> 4, r = u & 15;
        const float* wr = sWpos + r * 66;
        float acc = sbpos[r] + wr[sP[k]] + wr[40 + sAA[k]];
        const float* rb = sSmall + k * 32 + 16;
#pragma unroll
        for (int q = 0; q < 16; q++) acc = fmaf(rb[q], wr[16 + q], acc);
        const float* gm = sGm + k * 8;
#pragma unroll
        for (int g = 0; g < 8; g++) acc = fmaf(gm[g], wr[32 + g], acc);
        sSmall[k * 32 + r] = acc;
    }
    __syncthreads();

    // Phase B: s2 via LDS.128 (ulonglong2 = two packed f32x2 operands)
    {
        int c = tid;
        ull w2[16];
#pragma unroll
        for (int q2 = 0; q2 < 16; q2++) w2[q2] = __ldg(g_Wsm2P + q2 * 128 + c);
        float a = sA[c];
        size_t ebase = (size_t)i * K * 128;
        for (int k0 = 0; k0 < K; k0 += 4) {
            ull acc[4];
#pragma unroll
            for (int kk = 0; kk < 4; kk++)
                acc[kk] = pack2(a + __ldg(g_B + (size_t)sJ[k0 + kk] * 128 + c), 0.f);
#pragma unroll
            for (int kk = 0; kk < 4; kk++) {
                const ulonglong2* s4 = (const ulonglong2*)(sSmall + (k0 + kk) * 32);
#pragma unroll
                for (int q4 = 0; q4 < 8; q4++) {
                    ulonglong2 v = s4[q4];
                    acc[kk] = fma2(v.x, w2[q4 * 2], acc[kk]);
                    acc[kk] = fma2(v.y, w2[q4 * 2 + 1], acc[kk]);
                }
            }
#pragma unroll
            for (int kk = 0; kk < 4; kk++) {
                float e = lo2(acc[kk]) + hi2(acc[kk]);
                sE[(k0 + kk) * 132 + c] = e;
                __nv_bfloat16 h = __float2bfloat16(e);
                __nv_bfloat16 l = __float2bfloat16(e - __bfloat162float(h));
                g_Ehi[ebase + (size_t)(k0 + kk) * 128 + c] = h;
                g_Elo[ebase + (size_t)(k0 + kk) * 128 + c] = l;
            }
        }
    }
    __syncthreads();

    {
        int wrp = tid >> 5, lane = tid & 31;
        for (int k = wrp; k < K; k += 4) {
            float s = 0.f, ss = 0.f;
#pragma unroll
            for (int q = 0; q < 4; q++) {
                float v = sE[k * 132 + lane + q * 32];
                s += v;
                ss = fmaf(v, v, ss);
            }
#pragma unroll
            for (int off = 16; off > 0; off >>= 1) {
                s += __shfl_xor_sync(0xffffffffu, s, off);
                ss += __shfl_xor_sync(0xffffffffu, ss, off);
            }
            if (lane == 0) {
                float mean = s * (1.0f / 128.0f);
                float var = ss * (1.0f / 128.0f) - mean * mean;
                g_mean[i * K + k] = mean;
                g_rstd[i * K + k] = rsqrtf(var + 1e-5f);
            }
        }
    }
}

// ---------------- projection GEMM: 256-row M-tile (R11) ----------------
#define SSTR 136
#define EHI_OFF 0
#define ELO_OFF (256 * SSTR * 2)           // 69632
#define WHI_OFF (2 * 256 * SSTR * 2)       // 139264
#define WLO_OFF (WHI_OFF + 128 * SSTR * 2) // 174080
#define GEMM_SMEM (WLO_OFF + 128 * SSTR * 2) // 208896

__global__ void __launch_bounds__(256, 1) proj_gemm_kernel(float* __restrict__ out) {
    extern __shared__ __align__(16) char gsm[];
    uint32_t sb = smem_u32(gsm);
    int tid = threadIdx.x;
    int wid = tid >> 5, lane = tid & 31;
    int m0 = blockIdx.x * 256;

#pragma unroll
    for (int it = 0; it < 8; it++) {
        int vec = it * 256 + tid;
        int n = vec >> 4;
        int c8 = (vec & 15) << 3;
        uint32_t so = (uint32_t)n * (SSTR * 2) + c8 * 2;
        *(uint4*)(gsm + WHI_OFF + so) = __ldg((const uint4*)(g_WT_hi + (size_t)n * 128 + c8));
        *(uint4*)(gsm + WLO_OFF + so) = __ldg((const uint4*)(g_WT_lo + (size_t)n * 128 + c8));
    }
#pragma unroll
    for (int it = 0; it < 16; it++) {
        int vec = it * 256 + tid;
        int r = vec >> 4;
        int c8 = (vec & 15) << 3;
        uint32_t so = (uint32_t)r * (SSTR * 2) + c8 * 2;
        *(uint4*)(gsm + EHI_OFF + so) = __ldg((const uint4*)(g_Ehi + ((size_t)(m0 + r) << 7) + c8));
        *(uint4*)(gsm + ELO_OFF + so) = __ldg((const uint4*)(g_Elo + ((size_t)(m0 + r) << 7) + c8));
    }
    __syncthreads();

    int g = lane >> 3, ri = lane & 7;
    int n_base = (wid & 3) * 32;
    uint32_t boff[2];
#pragma unroll
    for (int nb = 0; nb < 2; nb++)
        boff[nb] = (uint32_t)((n_base + nb * 16 + ri + (g >> 1) * 8) * SSTR + (g & 1) * 8) * 2;

#pragma unroll
    for (int half = 0; half < 2; half++) {
        int m_base = half * 128 + (wid >> 2) * 64;
        uint32_t aoff[4];
#pragma unroll
        for (int mf = 0; mf < 4; mf++)
            aoff[mf] = (uint32_t)((m_base + mf * 16 + ri + (g & 1) * 8) * SSTR + (g >> 1) * 8) * 2;

        float acc[4][4][4];
#pragma unroll
        for (int mf = 0; mf < 4; mf++)
#pragma unroll
            for (int nf = 0; nf < 4; nf++)
#pragma unroll
                for (int q = 0; q < 4; q++) acc[mf][nf][q] = 0.f;

#pragma unroll
        for (int ks = 0; ks < 8; ks++) {
            uint32_t kb = ks * 32;
            uint32_t ah[4][4], al[4][4], bh[2][4], bl[2][4];
#pragma unroll
            for (int mf = 0; mf < 4; mf++) {
                ldm4(ah[mf], sb + EHI_OFF + aoff[mf] + kb);
                ldm4(al[mf], sb + ELO_OFF + aoff[mf] + kb);
            }
#pragma unroll
            for (int nb = 0; nb < 2; nb++) {
                ldm4(bh[nb], sb + WHI_OFF + boff[nb] + kb);
                ldm4(bl[nb], sb + WLO_OFF + boff[nb] + kb);
            }
#pragma unroll
            for (int mf = 0; mf < 4; mf++) {
#pragma unroll
                for (int nf = 0; nf < 4; nf++) {
                    const uint32_t* bhp = &bh[nf >> 1][(nf & 1) * 2];
                    const uint32_t* blp = &bl[nf >> 1][(nf & 1) * 2];
                    mma_bf16(acc[mf][nf], ah[mf], bhp);
                    mma_bf16(acc[mf][nf], ah[mf], blp);
                    mma_bf16(acc[mf][nf], al[mf], bhp);
                }
            }
        }

#pragma unroll
        for (int mf = 0; mf < 4; mf++) {
            int r0 = m0 + m_base + mf * 16 + (lane >> 2);
            float mean0 = __ldg(g_mean + r0), rstd0 = __ldg(g_rstd + r0);
            float mean1 = __ldg(g_mean + r0 + 8), rstd1 = __ldg(g_rstd + r0 + 8);
#pragma unroll
            for (int nf = 0; nf < 4; nf++) {
                int col = n_base + nf * 8 + (lane & 3) * 2;
                float2 w1v = *(const float2*)(g_w1 + col);
                float2 c0v = *(const float2*)(g_c0 + col);
                float2 o0, o1;
                o0.x = fmaf(rstd0, acc[mf][nf][0] - mean0 * w1v.x, c0v.x);
                o0.y = fmaf(rstd0, acc[mf][nf][1] - mean0 * w1v.y, c0v.y);
                o1.x = fmaf(rstd1, acc[mf][nf][2] - mean1 * w1v.x, c0v.x);
                o1.y = fmaf(rstd1, acc[mf][nf][3] - mean1 * w1v.y, c0v.y);
                *(float2*)(out + (size_t)r0 * 128 + col) = o0;
                *(float2*)(out + (size_t)(r0 + 8) * 128 + col) = o1;
            }
        }
    }
}

// ---------------- launch ----------------
extern "C" void kernel_launch(void* const* d_in, const int* in_sizes, int n_in,
                              void* d_out, int out_size) {
    const float* X        = (const float*)d_in[0];
    const float* node_h   = (const float*)d_in[1];
    const float* f_node   = (const float*)d_in[2];
    const float* Wpos     = (const float*)d_in[3];
    const float* bpos     = (const float*)d_in[4];
    const float* We       = (const float*)d_in[5];
    const float* ln_scale = (const float*)d_in[6];
    const float* ln_bias  = (const float*)d_in[7];
    const float* Wproj    = (const float*)d_in[8];
    const float* bproj    = (const float*)d_in[9];
    const int*   aatype   = (const int*)d_in[10];
    const int*   resi     = (const int*)d_in[11];
    float* out = (float*)d_out;

    cudaFuncSetAttribute(knn_kernel, cudaFuncAttributeMaxDynamicSharedMemorySize, 3 * L * 4);
    cudaFuncSetAttribute(features_kernel, cudaFuncAttributeMaxDynamicSharedMemorySize, F_TOT_B);
    cudaFuncSetAttribute(proj_gemm_kernel, cudaFuncAttributeMaxDynamicSharedMemorySize, GEMM_SMEM);

    prep_small_kernel<<<32, 256>>>(Wproj, ln_scale, ln_bias, bproj, We);
    prep_ab_kernel<<<L / 32, 128>>>(node_h, f_node);
    knn_kernel<<<L / 16, 512, 3 * L * 4>>>(X);
    features_kernel<<<L, 128, F_TOT_B>>>(X, Wpos, bpos, aatype, resi);
    proj_gemm_kernel<<<N_TILES2, 256, GEMM_SMEM>>>(out);
}

// round 16
// speedup vs baseline: 1.2226x; 1.0047x over previous
#include <cuda_runtime.h>
#include <cuda_bf16.h>
#include <cstdint>
#include <math.h>

#define L 8192
#define K 48
#define SENTK 0xFFFFFFFFFFFFFFFFULL
typedef unsigned long long ull;

#define M_EDGES (L * K)          // 393216
#define N_TILES2 (M_EDGES / 256) // 1536

// ---------------- device scratch (static; allocation-free) ----------------
__device__ __align__(16) float g_A[L * 128];
__device__ __align__(16) float g_B[L * 128];
__device__ __align__(16) ull   g_Wsm2P[16 * 128];
__device__ __align__(16) float g_WAT[128 * 128];
__device__ __align__(16) float g_WfT[128 * 128];
__device__ __align__(16) float g_WhT[128 * 128];
__device__ __align__(16) float g_w1[128];
__device__ __align__(16) float g_c0[128];
__device__ __align__(16) float g_Xt[3 * L];          // transposed coords [x:L][y:L][z:L]
__device__ __align__(16) __nv_bfloat16 g_WT_hi[128 * 128];
__device__ __align__(16) __nv_bfloat16 g_WT_lo[128 * 128];
__device__ int   g_knn_idx[L * K];
__device__ float g_knn_d[L * K];
__device__ __align__(16) __nv_bfloat16 g_Ehi[(size_t)M_EDGES * 128];
__device__ __align__(16) __nv_bfloat16 g_Elo[(size_t)M_EDGES * 128];
__device__ float g_mean[M_EDGES];
__device__ float g_rstd[M_EDGES];

// ---------------- helpers ----------------
__device__ __forceinline__ ull fma2(ull a, ull b, ull c) {
    ull d;
    asm("fma.rn.f32x2 %0, %1, %2, %3;" : "=l"(d) : "l"(a), "l"(b), "l"(c));
    return d;
}
__device__ __forceinline__ ull pack2(float lo, float hi) {
    ull d;
    asm("mov.b64 %0, {%1, %2};" : "=l"(d) : "r"(__float_as_uint(lo)), "r"(__float_as_uint(hi)));
    return d;
}
__device__ __forceinline__ float lo2(ull v) { return __uint_as_float((unsigned)v); }
__device__ __forceinline__ float hi2(ull v) { return __uint_as_float((unsigned)(v >> 32)); }

__device__ __forceinline__ uint32_t smem_u32(const void* p) {
    uint32_t a;
    asm("{ .reg .u64 t; cvta.to.shared.u64 t, %1; cvt.u32.u64 %0, t; }" : "=r"(a) : "l"(p));
    return a;
}
__device__ __forceinline__ void ldm4(uint32_t* r, uint32_t addr) {
    asm volatile("ldmatrix.sync.aligned.m8n8.x4.shared.b16 {%0,%1,%2,%3}, [%4];"
                 : "=r"(r[0]), "=r"(r[1]), "=r"(r[2]), "=r"(r[3]) : "r"(addr));
}
__device__ __forceinline__ void mma_bf16(float* c, const uint32_t* a, const uint32_t* b) {
    asm volatile("mma.sync.aligned.m16n8k16.row.col.f32.bf16.bf16.f32 "
                 "{%0,%1,%2,%3}, {%4,%5,%6,%7}, {%8,%9}, {%0,%1,%2,%3};"
                 : "+f"(c[0]), "+f"(c[1]), "+f"(c[2]), "+f"(c[3])
                 : "r"(a[0]), "r"(a[1]), "r"(a[2]), "r"(a[3]), "r"(b[0]), "r"(b[1]));
}

// ---------------- tiny precompute ----------------
__global__ void prep_small_kernel(const float* __restrict__ Wproj,
                                  const float* __restrict__ ln_scale,
                                  const float* __restrict__ ln_bias,
                                  const float* __restrict__ bproj,
                                  const float* __restrict__ We,
                                  const float* __restrict__ X) {
    int gid = blockIdx.x * blockDim.x + threadIdx.x;
    int NT = gridDim.x * blockDim.x;
    for (int n = gid; n < 16384; n += NT) {
        int c = n >> 7, t = n & 127;
        g_WAT[n] = We[t * 416 + 160 + c];
        g_WfT[n] = We[t * 416 + c];
        g_WhT[n] = We[t * 416 + 288 + c];
        int tt = n >> 7, cc = n & 127;
        float w = Wproj[tt * 128 + cc] * ln_scale[cc];
        __nv_bfloat16 h = __float2bfloat16(w);
        float res = w - __bfloat162float(h);
        g_WT_hi[n] = h;
        g_WT_lo[n] = __float2bfloat16(res);
    }
    for (int n = gid; n < 2048; n += NT) {
        int q2 = n >> 7, c = n & 127;
        g_Wsm2P[n] = pack2(We[c * 416 + 128 + 2 * q2], We[c * 416 + 128 + 2 * q2 + 1]);
    }
    for (int n = gid; n < L; n += NT) {
        g_Xt[n]         = X[3 * n];
        g_Xt[L + n]     = X[3 * n + 1];
        g_Xt[2 * L + n] = X[3 * n + 2];
    }
    if (gid < 128) {
        float s1 = 0.f, s0 = 0.f;
        for (int c = 0; c < 128; c++) {
            float w = Wproj[gid * 128 + c];
            s1 += w * ln_scale[c];
            s0 += w * ln_bias[c];
        }
        g_w1[gid] = s1;
        g_c0[gid] = s0 + bproj[gid];
    }
}

// ---------------- A/B tables ----------------
__global__ void __launch_bounds__(128) prep_ab_kernel(const float* __restrict__ node_h,
                                                      const float* __restrict__ f_node) {
    __shared__ float nh[32 * 128];
    __shared__ float fn[32 * 128];
    int tid = threadIdx.x;
    int i0 = blockIdx.x * 32;
    for (int f = tid; f < 32 * 128; f += 128) {
        nh[f] = node_h[i0 * 128 + f];
        fn[f] = f_node[i0 * 128 + f];
    }
    __syncthreads();
    for (int ch = 0; ch < 4; ch++) {
        float a[8], b[8];
#pragma unroll
        for (int ii = 0; ii < 8; ii++) { a[ii] = 0.f; b[ii] = 0.f; }
#pragma unroll 4
        for (int c = 0; c < 128; c++) {
            float wa = __ldg(g_WAT + c * 128 + tid);
            float wf = __ldg(g_WfT + c * 128 + tid);
            float wh = __ldg(g_WhT + c * 128 + tid);
#pragma unroll
            for (int ii = 0; ii < 8; ii++) {
                int row = ch * 8 + ii;
                float n = nh[row * 128 + c];
                float f = fn[row * 128 + c];
                a[ii] = fmaf(n, wa, a[ii]);
                b[ii] = fmaf(f, wf, fmaf(n, wh, b[ii]));
            }
        }
#pragma unroll
        for (int ii = 0; ii < 8; ii++) {
            g_A[(i0 + ch * 8 + ii) * 128 + tid] = a[ii];
            g_B[(i0 + ch * 8 + ii) * 128 + tid] = b[ii];
        }
    }
}

// ---------------- KNN: smem-free, L1-resident g_Xt, exact R11 scan/rounds ----------------
__global__ void __launch_bounds__(512) knn_kernel() {
    int tid = threadIdx.x;
    int lane = tid & 31;
    int i = blockIdx.x * 16 + (tid >> 5);
    const float* Xx = g_Xt;
    const float* Xy = g_Xt + L;
    const float* Xz = g_Xt + 2 * L;
    float xi = __ldg(Xx + i), yi = __ldg(Xy + i), zi = __ldg(Xz + i);

    ull h[8];
#pragma unroll
    for (int m = 0; m < 8; m++) h[m] = SENTK;

#pragma unroll 4
    for (int s = 0; s < L / 32; s++) {
        int j = lane + (s << 5);
        float dx = xi - __ldg(Xx + j), dy = yi - __ldg(Xy + j), dz = zi - __ldg(Xz + j);
        float ssq = __fadd_rn(__fadd_rn(__fmul_rn(dx, dx), __fmul_rn(dy, dy)), __fmul_rn(dz, dz));
        unsigned sb = __float_as_uint(ssq);
        unsigned hs = (unsigned)(h[7] >> 32);
        if (sb < hs || (sb == hs && (unsigned)j < (unsigned)h[7])) {
            h[7] = ((ull)sb << 32) | (unsigned)j;
#pragma unroll
            for (int m = 7; m > 0; m--)
                if (h[m] < h[m - 1]) { ull t = h[m]; h[m] = h[m - 1]; h[m - 1] = t; }
        }
    }

    ull mylast = 0ULL;
    for (int r = 0; r < K; r++) {
        if (h[0] == SENTK) {
            for (int s = 0; s < L / 32; s++) {
                int j = lane + (s << 5);
                float dx = xi - __ldg(Xx + j), dy = yi - __ldg(Xy + j), dz = zi - __ldg(Xz + j);
                float ssq = __fadd_rn(__fadd_rn(__fmul_rn(dx, dx), __fmul_rn(dy, dy)), __fmul_rn(dz, dz));
                ull key = ((ull)__float_as_uint(ssq) << 32) | (unsigned)j;
                if (key > mylast && key < h[7]) {
                    h[7] = key;
#pragma unroll
                    for (int m = 7; m > 0; m--)
                        if (h[m] < h[m - 1]) { ull t = h[m]; h[m] = h[m - 1]; h[m - 1] = t; }
                }
            }
        }
        unsigned hi = (unsigned)(h[0] >> 32);
        unsigned lo = (unsigned)h[0];
        unsigned hi_min = __reduce_min_sync(0xffffffffu, hi);
        unsigned lo_c = (hi == hi_min) ? lo : 0xffffffffu;
        unsigned lo_min = __reduce_min_sync(0xffffffffu, lo_c);
        ull mn = ((ull)hi_min << 32) | lo_min;
        if (h[0] == mn) {
            mylast = mn;
#pragma unroll
            for (int m = 0; m < 7; m++) h[m] = h[m + 1];
            h[7] = SENTK;
            g_knn_idx[i * K + r] = (int)lo_min;
            float ssq = __uint_as_float(hi_min);
            g_knn_d[i * K + r] = sqrtf(ssq + 1e-6f);
        }
    }
}

// ---------------- features: R15 (LDS.128 phase-B) ----------------
#define F_SE    0        // 48*132 = 6336
#define F_SML   6336     // 48*32  = 1536
#define F_SA    7872     // 128
#define F_SJ    8000     // 48 (int)
#define F_SD    8048     // 48
#define F_WPOS  8096     // 1056
#define F_BPOS  9152     // 16
#define F_GM    9168     // 384
#define F_P     9552     // 48 (int)
#define F_AA    9600     // 48 (int)
#define F_TOT_B 38592    // 9648 floats

__global__ void __launch_bounds__(128, 4) features_kernel(const float* __restrict__ X,
                                                          const float* __restrict__ Wpos,
                                                          const float* __restrict__ bpos,
                                                          const int* __restrict__ aatype,
                                                          const int* __restrict__ resi) {
    extern __shared__ float sm[];
    float* sE     = sm + F_SE;
    float* sSmall = sm + F_SML;
    float* sA     = sm + F_SA;
    int*   sJ     = (int*)(sm + F_SJ);
    float* sD     = sm + F_SD;
    float* sWpos  = sm + F_WPOS;
    float* sbpos  = sm + F_BPOS;
    float* sGm    = sm + F_GM;
    int*   sP     = (int*)(sm + F_P);
    int*   sAA    = (int*)(sm + F_AA);

    int tid = threadIdx.x;
    int i = blockIdx.x;

    if (tid < 32) ((float4*)sA)[tid] = ((const float4*)(g_A + (size_t)i * 128))[tid];
    if (tid < K) { sJ[tid] = g_knn_idx[i * K + tid]; sD[tid] = g_knn_d[i * K + tid]; }
    for (int n = tid; n < 1056; n += 128) sWpos[n] = __ldg(Wpos + n);
    if (tid >= 64 && tid < 80) sbpos[tid - 64] = __ldg(bpos + tid - 64);
    __syncthreads();

    if (tid < K) {
        int k = tid;
        int j = sJ[k];
        float d = sD[k];
#pragma unroll
        for (int q = 0; q < 16; q++) {
            float mu = 2.0f + (20.0f / 15.0f) * (float)q;
            float t = (d - mu) * 0.8f;
            sSmall[k * 32 + 16 + q] = expf(-t * t);
        }
        sGm[k * 8 + 0] = d * 0.1f;
        sGm[k * 8 + 1] = 1.0f / (1.0f + d);
        sGm[k * 8 + 2] = expf(-d);
        sGm[k * 8 + 3] = sinf(d);
        sGm[k * 8 + 4] = cosf(d);
        float inv = 1.0f / (d + 1e-6f);
        float xs = X[3 * i], ys = X[3 * i + 1], zs = X[3 * i + 2];
        sGm[k * 8 + 5] = (X[3 * j] - xs) * inv;
        sGm[k * 8 + 6] = (X[3 * j + 1] - ys) * inv;
        sGm[k * 8 + 7] = (X[3 * j + 2] - zs) * inv;
        int off = resi[j] - resi[i];
        sP[k] = min(max(off + 8, 0), 15);
        sAA[k] = aatype[j];
    }
    __syncthreads();

#pragma unroll
    for (int it = 0; it < 6; it++) {
        int u = it * 128 + tid;
        int k = u >> 4, r = u & 15;
        const float* wr = sWpos + r * 66;
        float acc = sbpos[r] + wr[sP[k]] + wr[40 + sAA[k]];
        const float* rb = sSmall + k * 32 + 16;
#pragma unroll
        for (int q = 0; q < 16; q++) acc = fmaf(rb[q], wr[16 + q], acc);
        const float* gm = sGm + k * 8;
#pragma unroll
        for (int g = 0; g < 8; g++) acc = fmaf(gm[g], wr[32 + g], acc);
        sSmall[k * 32 + r] = acc;
    }
    __syncthreads();

    {
        int c = tid;
        ull w2[16];
#pragma unroll
        for (int q2 = 0; q2 < 16; q2++) w2[q2] = __ldg(g_Wsm2P + q2 * 128 + c);
        float a = sA[c];
        size_t ebase = (size_t)i * K * 128;
        for (int k0 = 0; k0 < K; k0 += 4) {
            ull acc[4];
#pragma unroll
            for (int kk = 0; kk < 4; kk++)
                acc[kk] = pack2(a + __ldg(g_B + (size_t)sJ[k0 + kk] * 128 + c), 0.f);
#pragma unroll
            for (int kk = 0; kk < 4; kk++) {
                const ulonglong2* s4 = (const ulonglong2*)(sSmall + (k0 + kk) * 32);
#pragma unroll
                for (int q4 = 0; q4 < 8; q4++) {
                    ulonglong2 v = s4[q4];
                    acc[kk] = fma2(v.x, w2[q4 * 2], acc[kk]);
                    acc[kk] = fma2(v.y, w2[q4 * 2 + 1], acc[kk]);
                }
            }
#pragma unroll
            for (int kk = 0; kk < 4; kk++) {
                float e = lo2(acc[kk]) + hi2(acc[kk]);
                sE[(k0 + kk) * 132 + c] = e;
                __nv_bfloat16 h = __float2bfloat16(e);
                __nv_bfloat16 l = __float2bfloat16(e - __bfloat162float(h));
                g_Ehi[ebase + (size_t)(k0 + kk) * 128 + c] = h;
                g_Elo[ebase + (size_t)(k0 + kk) * 128 + c] = l;
            }
        }
    }
    __syncthreads();

    {
        int wrp = tid >> 5, lane = tid & 31;
        for (int k = wrp; k < K; k += 4) {
            float s = 0.f, ss = 0.f;
#pragma unroll
            for (int q = 0; q < 4; q++) {
                float v = sE[k * 132 + lane + q * 32];
                s += v;
                ss = fmaf(v, v, ss);
            }
#pragma unroll
            for (int off = 16; off > 0; off >>= 1) {
                s += __shfl_xor_sync(0xffffffffu, s, off);
                ss += __shfl_xor_sync(0xffffffffu, ss, off);
            }
            if (lane == 0) {
                float mean = s * (1.0f / 128.0f);
                float var = ss * (1.0f / 128.0f) - mean * mean;
                g_mean[i * K + k] = mean;
                g_rstd[i * K + k] = rsqrtf(var + 1e-5f);
            }
        }
    }
}

// ---------------- projection GEMM: 256-row M-tile (R11) ----------------
#define SSTR 136
#define EHI_OFF 0
#define ELO_OFF (256 * SSTR * 2)           // 69632
#define WHI_OFF (2 * 256 * SSTR * 2)       // 139264
#define WLO_OFF (WHI_OFF + 128 * SSTR * 2) // 174080
#define GEMM_SMEM (WLO_OFF + 128 * SSTR * 2) // 208896

__global__ void __launch_bounds__(256, 1) proj_gemm_kernel(float* __restrict__ out) {
    extern __shared__ __align__(16) char gsm[];
    uint32_t sb = smem_u32(gsm);
    int tid = threadIdx.x;
    int wid = tid >> 5, lane = tid & 31;
    int m0 = blockIdx.x * 256;

#pragma unroll
    for (int it = 0; it < 8; it++) {
        int vec = it * 256 + tid;
        int n = vec >> 4;
        int c8 = (vec & 15) << 3;
        uint32_t so = (uint32_t)n * (SSTR * 2) + c8 * 2;
        *(uint4*)(gsm + WHI_OFF + so) = __ldg((const uint4*)(g_WT_hi + (size_t)n * 128 + c8));
        *(uint4*)(gsm + WLO_OFF + so) = __ldg((const uint4*)(g_WT_lo + (size_t)n * 128 + c8));
    }
#pragma unroll
    for (int it = 0; it < 16; it++) {
        int vec = it * 256 + tid;
        int r = vec >> 4;
        int c8 = (vec & 15) << 3;
        uint32_t so = (uint32_t)r * (SSTR * 2) + c8 * 2;
        *(uint4*)(gsm + EHI_OFF + so) = __ldg((const uint4*)(g_Ehi + ((size_t)(m0 + r) << 7) + c8));
        *(uint4*)(gsm + ELO_OFF + so) = __ldg((const uint4*)(g_Elo + ((size_t)(m0 + r) << 7) + c8));
    }
    __syncthreads();

    int g = lane >> 3, ri = lane & 7;
    int n_base = (wid & 3) * 32;
    uint32_t boff[2];
#pragma unroll
    for (int nb = 0; nb < 2; nb++)
        boff[nb] = (uint32_t)((n_base + nb * 16 + ri + (g >> 1) * 8) * SSTR + (g & 1) * 8) * 2;

#pragma unroll
    for (int half = 0; half < 2; half++) {
        int m_base = half * 128 + (wid >> 2) * 64;
        uint32_t aoff[4];
#pragma unroll
        for (int mf = 0; mf < 4; mf++)
            aoff[mf] = (uint32_t)((m_base + mf * 16 + ri + (g & 1) * 8) * SSTR + (g >> 1) * 8) * 2;

        float acc[4][4][4];
#pragma unroll
        for (int mf = 0; mf < 4; mf++)
#pragma unroll
            for (int nf = 0; nf < 4; nf++)
#pragma unroll
                for (int q = 0; q < 4; q++) acc[mf][nf][q] = 0.f;

#pragma unroll
        for (int ks = 0; ks < 8; ks++) {
            uint32_t kb = ks * 32;
            uint32_t ah[4][4], al[4][4], bh[2][4], bl[2][4];
#pragma unroll
            for (int mf = 0; mf < 4; mf++) {
                ldm4(ah[mf], sb + EHI_OFF + aoff[mf] + kb);
                ldm4(al[mf], sb + ELO_OFF + aoff[mf] + kb);
            }
#pragma unroll
            for (int nb = 0; nb < 2; nb++) {
                ldm4(bh[nb], sb + WHI_OFF + boff[nb] + kb);
                ldm4(bl[nb], sb + WLO_OFF + boff[nb] + kb);
            }
#pragma unroll
            for (int mf = 0; mf < 4; mf++) {
#pragma unroll
                for (int nf = 0; nf < 4; nf++) {
                    const uint32_t* bhp = &bh[nf >> 1][(nf & 1) * 2];
                    const uint32_t* blp = &bl[nf >> 1][(nf & 1) * 2];
                    mma_bf16(acc[mf][nf], ah[mf], bhp);
                    mma_bf16(acc[mf][nf], ah[mf], blp);
                    mma_bf16(acc[mf][nf], al[mf], bhp);
                }
            }
        }

#pragma unroll
        for (int mf = 0; mf < 4; mf++) {
            int r0 = m0 + m_base + mf * 16 + (lane >> 2);
            float mean0 = __ldg(g_mean + r0), rstd0 = __ldg(g_rstd + r0);
            float mean1 = __ldg(g_mean + r0 + 8), rstd1 = __ldg(g_rstd + r0 + 8);
#pragma unroll
            for (int nf = 0; nf < 4; nf++) {
                int col = n_base + nf * 8 + (lane & 3) * 2;
                float2 w1v = *(const float2*)(g_w1 + col);
                float2 c0v = *(const float2*)(g_c0 + col);
                float2 o0, o1;
                o0.x = fmaf(rstd0, acc[mf][nf][0] - mean0 * w1v.x, c0v.x);
                o0.y = fmaf(rstd0, acc[mf][nf][1] - mean0 * w1v.y, c0v.y);
                o1.x = fmaf(rstd1, acc[mf][nf][2] - mean1 * w1v.x, c0v.x);
                o1.y = fmaf(rstd1, acc[mf][nf][3] - mean1 * w1v.y, c0v.y);
                *(float2*)(out + (size_t)r0 * 128 + col) = o0;
                *(float2*)(out + (size_t)(r0 + 8) * 128 + col) = o1;
            }
        }
    }
}

// ---------------- launch ----------------
extern "C" void kernel_launch(void* const* d_in, const int* in_sizes, int n_in,
                              void* d_out, int out_size) {
    const float* X        = (const float*)d_in[0];
    const float* node_h   = (const float*)d_in[1];
    const float* f_node   = (const float*)d_in[2];
    const float* Wpos     = (const float*)d_in[3];
    const float* bpos     = (const float*)d_in[4];
    const float* We       = (const float*)d_in[5];
    const float* ln_scale = (const float*)d_in[6];
    const float* ln_bias  = (const float*)d_in[7];
    const float* Wproj    = (const float*)d_in[8];
    const float* bproj    = (const float*)d_in[9];
    const int*   aatype   = (const int*)d_in[10];
    const int*   resi     = (const int*)d_in[11];
    float* out = (float*)d_out;

    cudaFuncSetAttribute(features_kernel, cudaFuncAttributeMaxDynamicSharedMemorySize, F_TOT_B);
    cudaFuncSetAttribute(proj_gemm_kernel, cudaFuncAttributeMaxDynamicSharedMemorySize, GEMM_SMEM);

    prep_small_kernel<<<32, 256>>>(Wproj, ln_scale, ln_bias, bproj, We, X);
    prep_ab_kernel<<<L / 32, 128>>>(node_h, f_node);
    knn_kernel<<<L / 16, 512>>>();
    features_kernel<<<L, 128, F_TOT_B>>>(X, Wpos, bpos, aatype, resi);
    proj_gemm_kernel<<<N_TILES2, 256, GEMM_SMEM>>>(out);
}